// round 9
// baseline (speedup 1.0000x reference)
#include <cuda_runtime.h>
#include <cuda_bf16.h>
#include <mma.h>
#include <math.h>
#include <cstdint>

using namespace nvcuda;
typedef __nv_bfloat16 bf16;

// ---------------- problem constants ----------------
#define NTOK 8192
#define EMB  768
#define HID  3072
#define QKVD 2304
#define NBH  96
#define SEQ  1024
#define HD   64
#define LN_EPS 1e-5f

// ---------------- device scratch ----------------
__device__ bf16  g_lnE [NTOK * 3 * EMB];
__device__ bf16  g_hidE[(size_t)NTOK * 3 * HID];
__device__ bf16  g_w1E [3 * EMB * HID];                  // expanded [3K, N] row-major
__device__ bf16  g_w2E [(size_t)3 * HID * QKVD];         // expanded [3K, N] row-major
__device__ float g_qkv [NTOK * QKVD];
__device__ bf16  g_qE  [(size_t)NBH * SEQ * 3 * HD];
__device__ bf16  g_kE  [(size_t)NBH * SEQ * 3 * HD];
__device__ bf16  g_vE  [(size_t)NBH * 3 * SEQ * HD];
__device__ float g_sc  [(size_t)NBH * SEQ * SEQ];
__device__ bf16  g_pE  [(size_t)NBH * 3 * SEQ * SEQ];
__device__ float g_ao  [NBH * SEQ * HD];
__device__ float g_x1  [NTOK * EMB];
__device__ float g_x2  [NTOK * EMB];

__device__ __forceinline__ void split2(float x, bf16& h, bf16& l) {
    h = __float2bfloat16(x);
    l = __float2bfloat16(x - __bfloat162float(h));
}

// ---------------- cp.async helpers ----------------
__device__ __forceinline__ uint32_t smem_u32(const void* p) {
    uint32_t a;
    asm("{ .reg .u64 t; cvta.to.shared.u64 t, %1; cvt.u32.u64 %0, t; }" : "=r"(a) : "l"(p));
    return a;
}
__device__ __forceinline__ void cpa16(uint32_t dst, const void* src) {
    asm volatile("cp.async.cg.shared.global [%0], [%1], 16;" :: "r"(dst), "l"(src));
}
#define CP_COMMIT() asm volatile("cp.async.commit_group;" ::: "memory")
#define CP_WAIT1()  asm volatile("cp.async.wait_group 1;" ::: "memory")

// ================= pipelined WMMA GEMM =================
// C[BM=128 x BN tile] = act(op(A) @ op(B) + bias)
// AL: 0 A row-major [M,K]; 1 A col-major [K,M]
// BL: 0 B row-major [K,N]; 1 B col-major [N,K]
// EP: 0 fp32 out, 1 fp32+bias, 2 bias+GELU+expanded bf16 (hi,lo,hi segments)
template <int BN, int AL, int BL, int EP>
__global__ void __launch_bounds__(256, (BN >= 256) ? 1 : 2)
gemm_p(const bf16* __restrict__ A, const bf16* __restrict__ B,
       const float* __restrict__ bias, void* __restrict__ Cv,
       int lda, int ldb, int Kexp, int ntot,
       long long sA, long long sB, long long sC)
{
    constexpr int BM  = 128;
    constexpr int WGM = (BN >= 128) ? 2 : 4;
    constexpr int WGN = 8 / WGM;
    constexpr int WMt = BM / WGM / 16;
    constexpr int WNt = BN / WGN / 16;
    constexpr int LA   = (AL == 0) ? 40 : 136;
    constexpr int ASTG = (AL == 0) ? BM * LA : 32 * LA;     // elems / stage
    constexpr int LB   = (BL == 0) ? BN + 8 : 40;
    constexpr int BSTG = (BL == 0) ? 32 * LB : BN * LB;
    constexpr int STG  = ASTG + BSTG;
    constexpr int LC   = BN + 4;
    constexpr int AOPS = 512;                               // 16B chunks per stage
    constexpr int BOPS = (BL == 0) ? 32 * (BN / 8) : BN * 4;
    constexpr int CH   = (BN >= 256) ? 2 : 1;               // epilogue row chunks
    constexpr int RCH  = BM / CH;

    extern __shared__ char smraw[];
    const uint32_t smb = smem_u32(smraw);
    const int tid = threadIdx.x, wid = tid >> 5;

    A += blockIdx.z * sA;
    B += blockIdx.z * sB;
    const int m0 = blockIdx.y * BM, n0 = blockIdx.x * BN;
    const int nk = Kexp >> 5;

    auto FILL = [&](int kc, int s) {
        const uint32_t ab = smb + s * (STG * 2);
        const uint32_t bb = ab + ASTG * 2;
        const int k0 = kc * 32;
#pragma unroll
        for (int i = 0; i < AOPS / 256; i++) {
            const int e = tid + i * 256;
            if (AL == 0) {
                const int r = e >> 2, v = e & 3;
                cpa16(ab + (r * LA + v * 8) * 2,
                      A + (long long)(m0 + r) * lda + k0 + v * 8);
            } else {
                const int r = e >> 4, v = e & 15;
                cpa16(ab + (r * LA + v * 8) * 2,
                      A + (long long)(k0 + r) * lda + m0 + v * 8);
            }
        }
#pragma unroll
        for (int i = 0; i < BOPS / 256; i++) {
            const int e = tid + i * 256;
            if (BL == 0) {
                const int r = e / (BN / 8), v = e % (BN / 8);
                cpa16(bb + (r * LB + v * 8) * 2,
                      B + (long long)(k0 + r) * ldb + n0 + v * 8);
            } else {
                const int r = e >> 2, v = e & 3;
                cpa16(bb + (r * LB + v * 8) * 2,
                      B + (long long)(n0 + r) * ldb + k0 + v * 8);
            }
        }
    };

    const int wm = (wid % WGM) * (BM / WGM);
    const int wn = (wid / WGM) * (BN / WGN);

    using ALay = typename std::conditional<AL == 0, wmma::row_major, wmma::col_major>::type;
    using BLay = typename std::conditional<BL == 0, wmma::row_major, wmma::col_major>::type;

    wmma::fragment<wmma::accumulator, 16, 16, 16, float> acc[WMt][WNt];
#pragma unroll
    for (int i = 0; i < WMt; i++)
#pragma unroll
        for (int j = 0; j < WNt; j++)
            wmma::fill_fragment(acc[i][j], 0.0f);

    // prologue: stages 0 and 1 in flight
    FILL(0, 0); CP_COMMIT();
    FILL(1, 1); CP_COMMIT();

    for (int kc = 0; kc < nk; kc++) {
        const int s = kc % 3;
        CP_WAIT1();
        __syncthreads();
        // issue next-next stage fill BEFORE compute so DMA overlaps MMA
        if (kc + 2 < nk) FILL(kc + 2, (kc + 2) % 3);
        CP_COMMIT();

        bf16* As = (bf16*)smraw + s * STG;
        bf16* Bs = As + ASTG;
#pragma unroll
        for (int kk = 0; kk < 32; kk += 16) {
            wmma::fragment<wmma::matrix_a, 16, 16, 16, bf16, ALay> af[WMt];
            wmma::fragment<wmma::matrix_b, 16, 16, 16, bf16, BLay> bfr[WNt];
#pragma unroll
            for (int i = 0; i < WMt; i++) {
                const bf16* p = (AL == 0) ? &As[(wm + i * 16) * LA + kk]
                                          : &As[kk * LA + wm + i * 16];
                wmma::load_matrix_sync(af[i], p, LA);
            }
#pragma unroll
            for (int j = 0; j < WNt; j++) {
                const bf16* p = (BL == 0) ? &Bs[kk * LB + wn + j * 16]
                                          : &Bs[(wn + j * 16) * LB + kk];
                wmma::load_matrix_sync(bfr[j], p, LB);
            }
#pragma unroll
            for (int i = 0; i < WMt; i++)
#pragma unroll
                for (int j = 0; j < WNt; j++)
                    wmma::mma_sync(acc[i][j], af[i], bfr[j], acc[i][j]);
        }
    }

    // chunked epilogue: stage RCH rows of C at a time, fused bias/GELU/expand
    float* Cs = (float*)smraw;
    float* Cf = (float*)Cv + blockIdx.z * sC;
    bf16*  Ce = (bf16*)Cv;
#pragma unroll
    for (int h = 0; h < CH; h++) {
        __syncthreads();
        if (wm / RCH == h) {
#pragma unroll
            for (int i = 0; i < WMt; i++)
#pragma unroll
                for (int j = 0; j < WNt; j++)
                    wmma::store_matrix_sync(&Cs[((wm % RCH) + i * 16) * LC + wn + j * 16],
                                            acc[i][j], LC, wmma::mem_row_major);
        }
        __syncthreads();
#pragma unroll
        for (int i = 0; i < RCH * BN / 256; i++) {
            const int e = tid + i * 256;
            const int r = e / BN, c = e % BN;
            float v = Cs[r * LC + c];
            if (EP >= 1) v += bias[n0 + c];
            const int gr = m0 + h * RCH + r;
            if (EP == 2) {
                v = 0.5f * v * (1.0f + erff(v * 0.70710678118654752f));
                const long long base = (long long)gr * (3LL * ntot) + n0 + c;
                bf16 hh, lo; split2(v, hh, lo);
                Ce[base] = hh; Ce[base + ntot] = lo; Ce[base + 2 * ntot] = hh;
            } else {
                Cf[(long long)gr * ntot + n0 + c] = v;
            }
        }
    }
}

// ---------------- LayerNorm -> expanded bf16 (A-style: hi, lo, hi) ----------------
__global__ void ln_exp_k(const float* __restrict__ x, const float* __restrict__ g,
                         const float* __restrict__ b, bf16* __restrict__ y)
{
    const long t = blockIdx.x;
    const float* xr = x + t * EMB;
    float v[3];
    float s = 0.f, s2 = 0.f;
#pragma unroll
    for (int i = 0; i < 3; i++) {
        v[i] = xr[threadIdx.x + i * 256];
        s += v[i]; s2 += v[i] * v[i];
    }
#pragma unroll
    for (int o = 16; o > 0; o >>= 1) {
        s  += __shfl_xor_sync(0xffffffffu, s,  o);
        s2 += __shfl_xor_sync(0xffffffffu, s2, o);
    }
    __shared__ float rs[8], rs2[8];
    const int w = threadIdx.x >> 5, l = threadIdx.x & 31;
    if (l == 0) { rs[w] = s; rs2[w] = s2; }
    __syncthreads();
    float ts = 0.f, ts2 = 0.f;
#pragma unroll
    for (int i = 0; i < 8; i++) { ts += rs[i]; ts2 += rs2[i]; }
    const float mean = ts * (1.0f / EMB);
    const float var  = ts2 * (1.0f / EMB) - mean * mean;
    const float inv  = rsqrtf(var + LN_EPS);
    bf16* yr = y + t * (3 * EMB);
#pragma unroll
    for (int i = 0; i < 3; i++) {
        const int c = threadIdx.x + i * 256;
        float val = (v[i] - mean) * inv * g[c] + b[c];
        bf16 h, lo; split2(val, h, lo);
        yr[c] = h; yr[EMB + c] = lo; yr[2 * EMB + c] = h;
    }
}

// ------- weight expansion (B-style: hi, hi, lo along K), [3K, N] row-major -------
__global__ void wexp_k(const float* __restrict__ W, bf16* __restrict__ We, int K, int N)
{
    const int idx = blockIdx.x * 256 + threadIdx.x;
    if (idx >= K * N) return;
    const int r = idx / N, c = idx - r * N;
    bf16 h, lo; split2(W[idx], h, lo);
    We[(long)r * N + c] = h;
    We[(long)(K + r) * N + c] = h;
    We[(long)(2 * K + r) * N + c] = lo;
}

// ---------------- split qkv -> expanded Q (A), K (B-col), V (B-row) ----------------
__global__ void split_qkv_exp_k(const float* __restrict__ qkv,
                                bf16* __restrict__ q, bf16* __restrict__ k,
                                bf16* __restrict__ v)
{
    const int idx = blockIdx.x * 256 + threadIdx.x;
    const int tok = idx / QKVD;
    const int c   = idx - tok * QKVD;
    const int kq  = c / (12 * HD);
    const int rem = c - kq * (12 * HD);
    const int n   = rem >> 6;
    const int s   = rem & 63;
    const int b   = tok >> 10;
    const int p   = tok & 1023;
    const int bh  = b * 12 + n;
    bf16 h, lo; split2(qkv[idx], h, lo);
    if (kq == 0) {
        const long base = (long)bh * (SEQ * 192) + p * 192 + s;
        q[base] = h; q[base + 64] = lo; q[base + 128] = h;
    } else if (kq == 1) {
        const long base = (long)bh * (SEQ * 192) + p * 192 + s;
        k[base] = h; k[base + 64] = h; k[base + 128] = lo;
    } else {
        const long base = (long)bh * (3 * SEQ * HD) + p * HD + s;
        v[base] = h; v[base + SEQ * HD] = h; v[base + 2 * SEQ * HD] = lo;
    }
}

// ---------------- softmax -> expanded bf16 P ----------------
__global__ void softmax_exp_k(const float* __restrict__ S, bf16* __restrict__ P)
{
    const long row = blockIdx.x;
    const int z = (int)(row >> 10), t = (int)(row & 1023);
    const float* p = S + row * SEQ;
    float v[4];
    float mx = -1e30f;
#pragma unroll
    for (int i = 0; i < 4; i++) {
        v[i] = p[threadIdx.x + i * 256] * 0.125f;
        mx = fmaxf(mx, v[i]);
    }
#pragma unroll
    for (int o = 16; o > 0; o >>= 1) mx = fmaxf(mx, __shfl_xor_sync(0xffffffffu, mx, o));
    __shared__ float rmax[8], rsum[8];
    const int w = threadIdx.x >> 5, l = threadIdx.x & 31;
    if (l == 0) rmax[w] = mx;
    __syncthreads();
    float m = rmax[0];
#pragma unroll
    for (int i = 1; i < 8; i++) m = fmaxf(m, rmax[i]);
    float s = 0.f;
#pragma unroll
    for (int i = 0; i < 4; i++) { v[i] = __expf(v[i] - m); s += v[i]; }
#pragma unroll
    for (int o = 16; o > 0; o >>= 1) s += __shfl_xor_sync(0xffffffffu, s, o);
    if (l == 0) rsum[w] = s;
    __syncthreads();
    float tot = 0.f;
#pragma unroll
    for (int i = 0; i < 8; i++) tot += rsum[i];
    const float inv = 1.0f / tot;
    bf16* out = P + (long)z * (3 * SEQ * SEQ) + (long)t * SEQ;
#pragma unroll
    for (int i = 0; i < 4; i++) {
        const int c = threadIdx.x + i * 256;
        bf16 h, lo; split2(v[i] * inv, h, lo);
        out[c] = h;
        out[c + SEQ * SEQ] = lo;
        out[c + 2 * SEQ * SEQ] = h;
    }
}

// ---------------- merge heads ----------------
__global__ void merge_heads_k(const float* __restrict__ ao, float* __restrict__ y)
{
    const int idx = blockIdx.x * 256 + threadIdx.x;
    const int tok = idx / EMB;
    const int c   = idx - tok * EMB;
    const int n   = c >> 6;
    const int s   = c & 63;
    const int b   = tok >> 10;
    const int p   = tok & 1023;
    y[idx] = ao[(long)(b * 12 + n) * (SEQ * HD) + p * HD + s];
}

// ---------------- host launcher ----------------
// dynamic smem per instantiation
#define SM_R256 81408  // stage=(128*40+32*264)*2=27136, 3x=81408; Cs chunk=64*260*4=66560
#define SM_RC   67584  // stage=(128*40+128*40)*2=20480, 3x=61440; Cs=128*132*4=67584
#define SM_PV   39936  // stage=(32*136+32*72)*2=13312, 3x=39936; Cs=128*68*4=34816

extern "C" void kernel_launch(void* const* d_in, const int* in_sizes, int n_in,
                              void* d_out, int out_size)
{
    const float* x       = (const float*)d_in[0];
    const float* qkv_g   = (const float*)d_in[1];
    const float* qkv_b   = (const float*)d_in[2];
    const float* qkv_W1  = (const float*)d_in[3];
    const float* qkv_b1  = (const float*)d_in[4];
    const float* qkv_W2  = (const float*)d_in[5];
    const float* qkv_b2  = (const float*)d_in[6];
    const float* proj_g  = (const float*)d_in[7];
    const float* proj_b  = (const float*)d_in[8];
    const float* proj_W1 = (const float*)d_in[9];
    const float* proj_b1 = (const float*)d_in[10];
    const float* proj_W2 = (const float*)d_in[11];
    const float* proj_b2 = (const float*)d_in[12];
    const float* mlp_g   = (const float*)d_in[13];
    const float* mlp_b   = (const float*)d_in[14];
    const float* mlp_W1  = (const float*)d_in[15];
    const float* mlp_b1  = (const float*)d_in[16];
    const float* mlp_W2  = (const float*)d_in[17];
    const float* mlp_b2  = (const float*)d_in[18];
    float* out = (float*)d_out;

    bf16 *lnE, *hidE, *w1E, *w2E, *qE, *kE, *vE, *pE;
    float *qkv, *sc, *ao, *x1, *x2;
    cudaGetSymbolAddress((void**)&lnE,  g_lnE);
    cudaGetSymbolAddress((void**)&hidE, g_hidE);
    cudaGetSymbolAddress((void**)&w1E,  g_w1E);
    cudaGetSymbolAddress((void**)&w2E,  g_w2E);
    cudaGetSymbolAddress((void**)&qkv,  g_qkv);
    cudaGetSymbolAddress((void**)&qE,   g_qE);
    cudaGetSymbolAddress((void**)&kE,   g_kE);
    cudaGetSymbolAddress((void**)&vE,   g_vE);
    cudaGetSymbolAddress((void**)&sc,   g_sc);
    cudaGetSymbolAddress((void**)&pE,   g_pE);
    cudaGetSymbolAddress((void**)&ao,   g_ao);
    cudaGetSymbolAddress((void**)&x1,   g_x1);
    cudaGetSymbolAddress((void**)&x2,   g_x2);

    cudaFuncSetAttribute(gemm_p<256,0,0,2>, cudaFuncAttributeMaxDynamicSharedMemorySize, SM_R256);
    cudaFuncSetAttribute(gemm_p<256,0,0,1>, cudaFuncAttributeMaxDynamicSharedMemorySize, SM_R256);
    cudaFuncSetAttribute(gemm_p<128,0,1,0>, cudaFuncAttributeMaxDynamicSharedMemorySize, SM_RC);
    cudaFuncSetAttribute(gemm_p<64,1,0,0>,  cudaFuncAttributeMaxDynamicSharedMemorySize, SM_PV);

    // ======== qkv block ========
    ln_exp_k<<<NTOK, 256>>>(x, qkv_g, qkv_b, lnE);
    wexp_k<<<(EMB * HID + 255) / 256, 256>>>(qkv_W1, w1E, EMB, HID);
    gemm_p<256,0,0,2><<<dim3(HID / 256, NTOK / 128, 1), 256, SM_R256>>>(
        lnE, w1E, qkv_b1, hidE, 3 * EMB, HID, 3 * EMB, HID, 0, 0, 0);
    wexp_k<<<(HID * QKVD + 255) / 256, 256>>>(qkv_W2, w2E, HID, QKVD);
    gemm_p<256,0,0,1><<<dim3(QKVD / 256, NTOK / 128, 1), 256, SM_R256>>>(
        hidE, w2E, qkv_b2, qkv, 3 * HID, QKVD, 3 * HID, QKVD, 0, 0, 0);

    // ======== attention ========
    split_qkv_exp_k<<<(NTOK * QKVD) / 256, 256>>>(qkv, qE, kE, vE);
    gemm_p<128,0,1,0><<<dim3(SEQ / 128, SEQ / 128, NBH), 256, SM_RC>>>(
        qE, kE, nullptr, sc, 192, 192, 192, SEQ,
        (long long)SEQ * 192, (long long)SEQ * 192, (long long)SEQ * SEQ);
    softmax_exp_k<<<NBH * SEQ, 256>>>(sc, pE);
    gemm_p<64,1,0,0><<<dim3(1, SEQ / 128, NBH), 256, SM_PV>>>(
        pE, vE, nullptr, ao, SEQ, HD, 3 * SEQ, HD,
        (long long)3 * SEQ * SEQ, (long long)3 * SEQ * HD, (long long)SEQ * HD);
    merge_heads_k<<<(NTOK * EMB) / 256, 256>>>(ao, x1);

    // ======== proj block ========
    ln_exp_k<<<NTOK, 256>>>(x1, proj_g, proj_b, lnE);
    wexp_k<<<(EMB * HID + 255) / 256, 256>>>(proj_W1, w1E, EMB, HID);
    gemm_p<256,0,0,2><<<dim3(HID / 256, NTOK / 128, 1), 256, SM_R256>>>(
        lnE, w1E, proj_b1, hidE, 3 * EMB, HID, 3 * EMB, HID, 0, 0, 0);
    wexp_k<<<(HID * EMB + 255) / 256, 256>>>(proj_W2, w2E, HID, EMB);
    gemm_p<256,0,0,1><<<dim3(EMB / 256, NTOK / 128, 1), 256, SM_R256>>>(
        hidE, w2E, proj_b2, x2, 3 * HID, EMB, 3 * HID, EMB, 0, 0, 0);

    // ======== mlp block ========
    ln_exp_k<<<NTOK, 256>>>(x2, mlp_g, mlp_b, lnE);
    wexp_k<<<(EMB * HID + 255) / 256, 256>>>(mlp_W1, w1E, EMB, HID);
    gemm_p<256,0,0,2><<<dim3(HID / 256, NTOK / 128, 1), 256, SM_R256>>>(
        lnE, w1E, mlp_b1, hidE, 3 * EMB, HID, 3 * EMB, HID, 0, 0, 0);
    wexp_k<<<(HID * EMB + 255) / 256, 256>>>(mlp_W2, w2E, HID, EMB);
    gemm_p<256,0,0,1><<<dim3(EMB / 256, NTOK / 128, 1), 256, SM_R256>>>(
        hidE, w2E, mlp_b2, out, 3 * HID, EMB, 3 * HID, EMB, 0, 0, 0);
}